// round 13
// baseline (speedup 1.0000x reference)
#include <cuda_runtime.h>
#include <math_constants.h>

#define HH 512
#define WW 512
#define NIMG 24          // 8 * 3 image slices per tensor
#define NBINS 362
#define NPIX (HH * WW)
#define NK 257           // stored spectrum columns 0..256 (Hermitian)

// ---------------------------------------------------------------------------
// Transposed scratch: g_fftT[tens][img][k*512 + y] = row-FFT(row y)[freq k]
__device__ float2 g_fftT[2][NIMG][NK * HH];
__device__ float  g_Smag[NIMG][NBINS];
__device__ float  g_Sd[NIMG][NBINS];
__device__ float  g_cnt[NBINS];
__device__ unsigned g_done;

__device__ __forceinline__ int rev5(int x) { return (int)(__brev((unsigned)x) >> 27); }

__device__ __forceinline__ float2 cmul(float2 a, float2 b) {
    return make_float2(a.x * b.x - a.y * b.y, a.x * b.y + a.y * b.x);
}

// Exact floor(sqrt(rsq)) for rsq = M + 0.5 (M integer <= 130560, exactly
// representable). sqrt(M+0.5) is never closer than 0.25/361 ~ 6.9e-4 to an
// integer, far above MUFU.SQRT error -> plain truncation is exact.
__device__ __forceinline__ int ibin(float rsq) {
    float ra;
    asm("sqrt.approx.f32 %0, %1;" : "=f"(ra) : "f"(rsq));
    return (int)ra;
}

// ---------------------------------------------------------------------------
// Fully register-resident 512-pt radix-2 DIT FFT per warp.
// Input: reg[r] = x[rev9(lane*16+r)]. Output: natural order, t = lane*16+r.
// tw[k] = exp(-2*pi*i*k/512), k in [0,256).
__device__ __forceinline__ void rfft512(float2 reg[16], int lane, const float2* tw) {
    const float c16[8] = { 1.f,  0.92387953f,  0.70710678f,  0.38268343f,
                           0.f, -0.38268343f, -0.70710678f, -0.92387953f };
    const float s16[8] = { 0.f, -0.38268343f, -0.70710678f, -0.92387953f,
                          -1.f, -0.92387953f, -0.70710678f, -0.38268343f };
#pragma unroll
    for (int s = 1; s <= 4; s++) {
        const int half = 1 << (s - 1);
#pragma unroll
        for (int b = 0; b < 8; b++) {
            int j  = b & (half - 1);
            int i0 = ((b >> (s - 1)) << s) + j;
            int i1 = i0 + half;
            int ji = j << (4 - s);
            float2 u = reg[i0], v = reg[i1];
            float2 wv = make_float2(v.x * c16[ji] - v.y * s16[ji],
                                    v.x * s16[ji] + v.y * c16[ji]);
            reg[i0] = make_float2(u.x + wv.x, u.y + wv.y);
            reg[i1] = make_float2(u.x - wv.x, u.y - wv.y);
        }
    }
    // stages 5-9: cross-lane, pre-twiddle form
#pragma unroll
    for (int s = 5; s <= 9; s++) {
        const int L = 1 << (s - 5);
        const bool  up  = (lane & L) != 0;
        const float sgn = up ? -1.f : 1.f;
        float2 E = make_float2(1.f, 0.f);
        if (s >= 7) E = tw[(lane & (L - 1)) << (13 - s)];
#pragma unroll
        for (int r = 0; r < 16; r++) {
            float2 x = reg[r];
            float2 wx;
            if (s == 5)      wx = cmul(x, tw[r << 4]);
            else if (s == 6) wx = cmul(x, tw[((lane & 1) << 7) + (r << 3)]);
            else             wx = cmul(cmul(x, E), tw[(r << 4) >> (s - 5)]);
            float yx = up ? wx.x : x.x;
            float yy = up ? wx.y : x.y;
            float ox = __shfl_xor_sync(0xffffffffu, yx, L);
            float oy = __shfl_xor_sync(0xffffffffu, yy, L);
            reg[r].x = fmaf(sgn, yx, ox);
            reg[r].y = fmaf(sgn, yy, oy);
        }
    }
}

// ---------------------------------------------------------------------------
// Pass 1: row FFTs (2 real rows packed per complex FFT), register Hermitian
// unpack via shfl with A/B stores split between half-warps, transposed store
// through a swizzled smem tile. 8 warps/block = 16 rows.
__global__ void __launch_bounds__(256) kfft_rows(const float* __restrict__ pred,
                                                 const float* __restrict__ tgt) {
    __shared__ float2 ttile[NK * 17];   // [k][y ^ ((k>>4)&15)], stride 17
    __shared__ float2 tw[256];
    const int REV4[16] = {0,8,4,12,2,10,6,14,1,9,5,13,3,11,7,15};

    int tid = threadIdx.x;
    int bid = blockIdx.x;

    if (bid < 18) {   // folded accumulator zeroing (rows precede cols)
        for (int i = bid * 256 + tid; i < NIMG * NBINS; i += 18 * 256) {
            ((float*)g_Smag)[i] = 0.0f;
            ((float*)g_Sd)[i]   = 0.0f;
        }
        if (bid == 0) {
            for (int i = tid; i < NBINS; i += 256) g_cnt[i] = 0.0f;
            if (tid == 0) g_done = 0u;
        }
    }
    {
        float sn, cs;
        sincospif(-(float)tid / 256.0f, &sn, &cs);
        tw[tid] = make_float2(cs, sn);
    }

    int slice = bid >> 5;
    int pg    = bid & 31;
    int tens  = (slice >= NIMG) ? 1 : 0;
    int img   = tens ? slice - NIMG : slice;
    const float* src = tens ? tgt : pred;

    int w = tid >> 5, lane = tid & 31;
    int y0 = pg * 16;
    const float* rowA = src + ((size_t)img << 18) + ((size_t)(y0 + 2 * w) << 9);
    const float* rowB = rowA + HH;
    int lr = rev5(lane);

    float2 reg[16];
#pragma unroll
    for (int r = 0; r < 16; r++) {
        int s = REV4[r] * 32 + lr;
        reg[r] = make_float2(rowA[s], rowB[s]);
    }
    __syncthreads();                 // tw ready

    rfft512(reg, lane, tw);

    // Hermitian unpack: A[k]=(Z1+conj(Z2))/2, B[k]=(Z1-conj(Z2))/2i
    // r=0: k multiples of 16 (incl 256); partner (32-lane)&31, reg 0.
    {
        int k0 = lane << 4;
        int p0 = (32 - lane) & 31;
        float zx = __shfl_sync(0xffffffffu, reg[0].x, p0);
        float zy = __shfl_sync(0xffffffffu, reg[0].y, p0);
        if (k0 <= 256) {
            int fk = (k0 >> 4) & 15;
            float2 Z1 = reg[0];
            ttile[k0 * 17 + ((2 * w) ^ fk)]       = make_float2(0.5f * (Z1.x + zx), 0.5f * (Z1.y - zy));
            ttile[k0 * 17 + (((2 * w) ^ fk) ^ 1)] = make_float2(0.5f * (Z1.y + zy), 0.5f * (zx - Z1.x));
        }
    }
    // r=1..15: one shfl serves both halves.
#pragma unroll
    for (int r = 1; r < 16; r++) {
        float zx = __shfl_sync(0xffffffffu, reg[16 - r].x, lane ^ 31);
        float zy = __shfl_sync(0xffffffffu, reg[16 - r].y, lane ^ 31);
        if (lane < 16) {
            int k = (lane << 4) + r;
            float2 Z1 = reg[r];
            ttile[k * 17 + ((2 * w) ^ lane)] =
                make_float2(0.5f * (Z1.x + zx), 0.5f * (Z1.y - zy));
        } else {
            int L = lane ^ 31;
            int k = (L << 4) + 16 - r;
            float2 Z2 = reg[r];
            ttile[k * 17 + (((2 * w) ^ L) ^ 1)] =
                make_float2(0.5f * (zy + Z2.y), 0.5f * (Z2.x - zx));
        }
    }
    __syncthreads();

    // coalesced transposed store: 16 consecutive y per k = 128B lines
    float2* outp = g_fftT[tens][img];
    for (int i = tid; i < NK * 16; i += 256) {
        int k = i >> 4, y = i & 15;
        outp[k * 512 + y0 + y] = ttile[k * 17 + (y ^ ((k >> 4) & 15))];
    }
}

// ---------------------------------------------------------------------------
// Pass 2: column register FFTs for kx = 0..256 + direct global RED.ADD
// histogram flushes (no shared atomics) + fused finalize in the last block.
__global__ void __launch_bounds__(256, 3) kfft_cols(float* __restrict__ out) {
    __shared__ float2 tw[256];
    __shared__ double wacc[8];
    __shared__ unsigned slast;
    const int REV4[16] = {0,8,4,12,2,10,6,14,1,9,5,13,3,11,7,15};

    int tid = threadIdx.x;
    {
        float sn, cs;
        sincospif(-(float)tid / 256.0f, &sn, &cs);
        tw[tid] = make_float2(cs, sn);
    }
    __syncthreads();

    int bid = blockIdx.x;
    int img = bid / 33;
    int c0  = (bid % 33) << 3;
    bool docnt = (img == 0);

    float* Smag = g_Smag[img];
    float* Sd   = g_Sd[img];

    int w = tid >> 5, lane = tid & 31;
    int c = c0 + w;

    if (c <= 256) {
        const float2* colP = &g_fftT[0][img][(size_t)c * 512];
        const float2* colT = &g_fftT[1][img][(size_t)c * 512];
        int lr = rev5(lane);

        float2 reg[16];
        // target first: keep only |T|^2 in registers
#pragma unroll
        for (int r = 0; r < 16; r++) reg[r] = colT[REV4[r] * 32 + lr];
        rfft512(reg, lane, tw);
        float t2[16];
#pragma unroll
        for (int r = 0; r < 16; r++) t2[r] = reg[r].x * reg[r].x + reg[r].y * reg[r].y;

        // pred
#pragma unroll
        for (int r = 0; r < 16; r++) reg[r] = colP[REV4[r] * 32 + lr];
        rfft512(reg, lane, tw);

        bool dup = (c >= 1 && c <= 255);
        float sx   = (float)((c + 256) & 511) - 255.5f;
        float sxm  = 0.5f - (float)c;
        float sx2  = sx * sx;
        float sxm2 = sxm * sxm;

        // run-aggregated binning, flushed straight to L2 via RED.ADD.F32
        int   pb1 = -1, pb2 = -1;
        float am1 = 0.f, ad1 = 0.f, cn1 = 0.f;
        float am2 = 0.f, ad2 = 0.f, cn2 = 0.f;
#pragma unroll
        for (int r = 0; r < 16; r++) {
            int ky = lane * 16 + r;
            float2 P = reg[r];
            float p2 = P.x * P.x + P.y * P.y;
            float re = P.x + 1e-8f;
            float mag = 10.0f * __logf(re * re + P.y * P.y);  // 20*ln|re+eps+i*im|
            float df = p2 - t2[r];
            float d  = df * df;

            float sy = (float)((ky + 256) & 511) - 255.5f;
            int b1 = ibin(sx2 + sy * sy);
            if (b1 != pb1) {
                if (pb1 >= 0) {
                    atomicAdd(Smag + pb1, am1);
                    atomicAdd(Sd   + pb1, ad1);
                    if (docnt) atomicAdd(g_cnt + pb1, cn1);
                }
                pb1 = b1; am1 = 0.f; ad1 = 0.f; cn1 = 0.f;
            }
            am1 += mag; ad1 += d; cn1 += 1.f;

            if (dup) {   // conjugate-mirror pixel: same mag/d, mirrored bin
                int   ky2 = (512 - ky) & 511;
                float sy2 = (float)((ky2 + 256) & 511) - 255.5f;
                int b2 = ibin(sxm2 + sy2 * sy2);
                if (b2 != pb2) {
                    if (pb2 >= 0) {
                        atomicAdd(Smag + pb2, am2);
                        atomicAdd(Sd   + pb2, ad2);
                        if (docnt) atomicAdd(g_cnt + pb2, cn2);
                    }
                    pb2 = b2; am2 = 0.f; ad2 = 0.f; cn2 = 0.f;
                }
                am2 += mag; ad2 += d; cn2 += 1.f;
            }
        }
        if (pb1 >= 0) {
            atomicAdd(Smag + pb1, am1);
            atomicAdd(Sd   + pb1, ad1);
            if (docnt) atomicAdd(g_cnt + pb1, cn1);
        }
        if (pb2 >= 0) {
            atomicAdd(Smag + pb2, am2);
            atomicAdd(Sd   + pb2, ad2);
            if (docnt) atomicAdd(g_cnt + pb2, cn2);
        }
    }

    // ---- fused finalize: last block to flush does the per-image reduce ----
    __syncthreads();
    if (tid == 0) {
        __threadfence();
        slast = (atomicAdd(&g_done, 1u) == (unsigned)(gridDim.x - 1)) ? 1u : 0u;
    }
    __syncthreads();
    if (!slast) return;
    __threadfence();   // acquire: all other blocks' REDs visible

    // 8 warps x 3 images each; shuffle-only per-image normalize + dot
    double acc = 0.0;
#pragma unroll
    for (int j = 0; j < 3; j++) {
        int im = w + (j << 3);
        float bm[12];
        float mn = CUDART_INF_F, mx = -CUDART_INF_F;
#pragma unroll
        for (int i = 0; i < 12; i++) {
            int b = lane + (i << 5);
            float v = 0.0f;
            if (b < NBINS) v = g_Smag[im][b] / g_cnt[b];
            bm[i] = v;
            if (b >= 1 && b <= 360) { mn = fminf(mn, v); mx = fmaxf(mx, v); }
        }
#pragma unroll
        for (int o = 16; o > 0; o >>= 1) {
            mn = fminf(mn, __shfl_xor_sync(0xffffffffu, mn, o));
            mx = fmaxf(mx, __shfl_xor_sync(0xffffffffu, mx, o));
        }
        float bm1 = __shfl_sync(0xffffffffu, bm[0], 1);   // bin-1 mean (for bin 0)
#pragma unroll
        for (int i = 0; i < 12; i++) {
            int b = lane + (i << 5);
            if (b < NBINS) {
                float psdext;
                if (b == 361)    psdext = 0.0f;
                else {
                    float base = (b == 0) ? bm1 : bm[i];  // psd_ext[0]==psd_ext[1]
                    psdext = (base - mn) / (mx - mn);
                }
                float wv = 1.0f - psdext;
                if (!(wv == wv)) wv = 0.0f;               // nan -> 0
                wv = fminf(fmaxf(wv, 0.0f), 1.0f);        // clip
                acc += (double)wv * (double)g_Sd[im][b];
            }
        }
    }
#pragma unroll
    for (int o = 16; o > 0; o >>= 1)
        acc += __shfl_xor_sync(0xffffffffu, acc, o);
    if (lane == 0) wacc[w] = acc;
    __syncthreads();
    if (tid == 0) {
        double tot = 0.0;
        for (int i = 0; i < 8; i++) tot += wacc[i];
        out[0] = (float)(tot / ((double)NIMG * (double)NPIX));
    }
}

// ---------------------------------------------------------------------------
extern "C" void kernel_launch(void* const* d_in, const int* in_sizes, int n_in,
                              void* d_out, int out_size) {
    const float* pred = (const float*)d_in[0];
    const float* tgt  = (const float*)d_in[1];
    float* out = (float*)d_out;

    kfft_rows<<<48 * 32, 256>>>(pred, tgt);
    kfft_cols<<<NIMG * 33, 256>>>(out);
}

// round 14
// speedup vs baseline: 1.9633x; 1.9633x over previous
#include <cuda_runtime.h>
#include <math_constants.h>

#define HH 512
#define WW 512
#define NIMG 24          // 8 * 3 image slices per tensor
#define NBINS 362
#define NPIX (HH * WW)
#define NK 257           // stored spectrum columns 0..256 (Hermitian)
#define FULLM 0xffffffffu

// ---------------------------------------------------------------------------
// Transposed scratch: g_fftT[tens][img][k*512 + y] = row-FFT(row y)[freq k]
__device__ float2 g_fftT[2][NIMG][NK * HH];
__device__ float  g_Smag[NIMG][NBINS];
__device__ float  g_Sd[NIMG][NBINS];
__device__ float  g_cnt[NBINS];
__device__ unsigned g_done;

__device__ __forceinline__ int rev5(int x) { return (int)(__brev((unsigned)x) >> 27); }

__device__ __forceinline__ float2 cmul(float2 a, float2 b) {
    return make_float2(a.x * b.x - a.y * b.y, a.x * b.y + a.y * b.x);
}

// Exact floor(sqrt(rsq)) for rsq = M + 0.5 (exactly representable; gap to any
// integer root >= 0.25/361 >> MUFU.SQRT error) -> plain truncation is exact.
__device__ __forceinline__ int ibin(float rsq) {
    float ra;
    asm("sqrt.approx.f32 %0, %1;" : "=f"(ra) : "f"(rsq));
    return (int)ra;
}

// ---------------------------------------------------------------------------
// Fully register-resident 512-pt radix-2 DIT FFT per warp.
// Input: reg[r] = x[rev9(lane*16+r)]. Output: natural order, t = lane*16+r.
__device__ __forceinline__ void rfft512(float2 reg[16], int lane, const float2* tw) {
    const float c16[8] = { 1.f,  0.92387953f,  0.70710678f,  0.38268343f,
                           0.f, -0.38268343f, -0.70710678f, -0.92387953f };
    const float s16[8] = { 0.f, -0.38268343f, -0.70710678f, -0.92387953f,
                          -1.f, -0.92387953f, -0.70710678f, -0.38268343f };
#pragma unroll
    for (int s = 1; s <= 4; s++) {
        const int half = 1 << (s - 1);
#pragma unroll
        for (int b = 0; b < 8; b++) {
            int j  = b & (half - 1);
            int i0 = ((b >> (s - 1)) << s) + j;
            int i1 = i0 + half;
            int ji = j << (4 - s);
            float2 u = reg[i0], v = reg[i1];
            float2 wv = make_float2(v.x * c16[ji] - v.y * s16[ji],
                                    v.x * s16[ji] + v.y * c16[ji]);
            reg[i0] = make_float2(u.x + wv.x, u.y + wv.y);
            reg[i1] = make_float2(u.x - wv.x, u.y - wv.y);
        }
    }
#pragma unroll
    for (int s = 5; s <= 9; s++) {
        const int L = 1 << (s - 5);
        const bool  up  = (lane & L) != 0;
        const float sgn = up ? -1.f : 1.f;
        float2 E = make_float2(1.f, 0.f);
        if (s >= 7) E = tw[(lane & (L - 1)) << (13 - s)];
#pragma unroll
        for (int r = 0; r < 16; r++) {
            float2 x = reg[r];
            float2 wx;
            if (s == 5)      wx = cmul(x, tw[r << 4]);
            else if (s == 6) wx = cmul(x, tw[((lane & 1) << 7) + (r << 3)]);
            else             wx = cmul(cmul(x, E), tw[(r << 4) >> (s - 5)]);
            float yx = up ? wx.x : x.x;
            float yy = up ? wx.y : x.y;
            float ox = __shfl_xor_sync(FULLM, yx, L);
            float oy = __shfl_xor_sync(FULLM, yy, L);
            reg[r].x = fmaf(sgn, yx, ox);
            reg[r].y = fmaf(sgn, yy, oy);
        }
    }
}

// ---------------------------------------------------------------------------
// Pass 1: row FFTs (2 real rows packed per complex FFT), register Hermitian
// unpack via shfl with A/B stores split between half-warps, transposed store
// through a swizzled smem tile. 8 warps/block = 16 rows.
__global__ void __launch_bounds__(256) kfft_rows(const float* __restrict__ pred,
                                                 const float* __restrict__ tgt) {
    __shared__ float2 ttile[NK * 17];   // [k][y ^ ((k>>4)&15)], stride 17
    __shared__ float2 tw[256];
    const int REV4[16] = {0,8,4,12,2,10,6,14,1,9,5,13,3,11,7,15};

    int tid = threadIdx.x;
    int bid = blockIdx.x;

    if (bid < 18) {   // folded accumulator zeroing (rows precede cols)
        for (int i = bid * 256 + tid; i < NIMG * NBINS; i += 18 * 256) {
            ((float*)g_Smag)[i] = 0.0f;
            ((float*)g_Sd)[i]   = 0.0f;
        }
        if (bid == 0) {
            for (int i = tid; i < NBINS; i += 256) g_cnt[i] = 0.0f;
            if (tid == 0) g_done = 0u;
        }
    }
    {
        float sn, cs;
        sincospif(-(float)tid / 256.0f, &sn, &cs);
        tw[tid] = make_float2(cs, sn);
    }

    int slice = bid >> 5;
    int pg    = bid & 31;
    int tens  = (slice >= NIMG) ? 1 : 0;
    int img   = tens ? slice - NIMG : slice;
    const float* src = tens ? tgt : pred;

    int w = tid >> 5, lane = tid & 31;
    int y0 = pg * 16;
    const float* rowA = src + ((size_t)img << 18) + ((size_t)(y0 + 2 * w) << 9);
    const float* rowB = rowA + HH;
    int lr = rev5(lane);

    float2 reg[16];
#pragma unroll
    for (int r = 0; r < 16; r++) {
        int s = REV4[r] * 32 + lr;
        reg[r] = make_float2(rowA[s], rowB[s]);
    }
    __syncthreads();                 // tw ready

    rfft512(reg, lane, tw);

    // Hermitian unpack: A[k]=(Z1+conj(Z2))/2, B[k]=(Z1-conj(Z2))/2i
    {
        int k0 = lane << 4;
        int p0 = (32 - lane) & 31;
        float zx = __shfl_sync(FULLM, reg[0].x, p0);
        float zy = __shfl_sync(FULLM, reg[0].y, p0);
        if (k0 <= 256) {
            int fk = (k0 >> 4) & 15;
            float2 Z1 = reg[0];
            ttile[k0 * 17 + ((2 * w) ^ fk)]       = make_float2(0.5f * (Z1.x + zx), 0.5f * (Z1.y - zy));
            ttile[k0 * 17 + (((2 * w) ^ fk) ^ 1)] = make_float2(0.5f * (Z1.y + zy), 0.5f * (zx - Z1.x));
        }
    }
#pragma unroll
    for (int r = 1; r < 16; r++) {
        float zx = __shfl_sync(FULLM, reg[16 - r].x, lane ^ 31);
        float zy = __shfl_sync(FULLM, reg[16 - r].y, lane ^ 31);
        if (lane < 16) {
            int k = (lane << 4) + r;
            float2 Z1 = reg[r];
            ttile[k * 17 + ((2 * w) ^ lane)] =
                make_float2(0.5f * (Z1.x + zx), 0.5f * (Z1.y - zy));
        } else {
            int L = lane ^ 31;
            int k = (L << 4) + 16 - r;
            float2 Z2 = reg[r];
            ttile[k * 17 + (((2 * w) ^ L) ^ 1)] =
                make_float2(0.5f * (zy + Z2.y), 0.5f * (Z2.x - zx));
        }
    }
    __syncthreads();

    float2* outp = g_fftT[tens][img];
    for (int i = tid; i < NK * 16; i += 256) {
        int k = i >> 4, y = i & 15;
        outp[k * 512 + y0 + y] = ttile[k * 17 + (y ^ ((k >> 4) & 15))];
    }
}

// ---------------------------------------------------------------------------
// Pass 2: column register FFTs for kx = 0..256. Binning uses mirror-symmetry
// pair aggregation: lanes 0-15 bin the main column (self + 511-ky partner
// pre-summed via shfl), lanes 16-31 bin the Hermitian mirror column 512-c
// (values gathered + pair-summed via shfl). Halves ATOMS lane-ops.
__global__ void __launch_bounds__(256, 3) kfft_cols(float* __restrict__ out) {
    __shared__ float2 tw[256];
    __shared__ float  sbm[NBINS], sbd[NBINS], scn[NBINS];
    __shared__ float  dpark[8][512];
    __shared__ double wacc[8];
    __shared__ unsigned slast;
    const int REV4[16] = {0,8,4,12,2,10,6,14,1,9,5,13,3,11,7,15};

    int tid = threadIdx.x;
    {
        float sn, cs;
        sincospif(-(float)tid / 256.0f, &sn, &cs);
        tw[tid] = make_float2(cs, sn);
    }
    for (int i = tid; i < NBINS; i += 256) { sbm[i] = 0.0f; sbd[i] = 0.0f; scn[i] = 0.0f; }
    __syncthreads();

    int bid = blockIdx.x;
    int img = bid / 33;
    int c0  = (bid % 33) << 3;
    bool docnt = (img == 0);

    int w = tid >> 5, lane = tid & 31;
    int c = c0 + w;

    if (c <= 256) {
        const float2* colP = &g_fftT[0][img][(size_t)c * 512];
        const float2* colT = &g_fftT[1][img][(size_t)c * 512];
        int lr = rev5(lane);

        float2 reg[16];
        // target: |T|^2 in registers
#pragma unroll
        for (int r = 0; r < 16; r++) reg[r] = colT[REV4[r] * 32 + lr];
        rfft512(reg, lane, tw);
        float t2[16];
#pragma unroll
        for (int r = 0; r < 16; r++) t2[r] = reg[r].x * reg[r].x + reg[r].y * reg[r].y;

        // pred: mag kept in regs, d parked in conflict-free smem
#pragma unroll
        for (int r = 0; r < 16; r++) reg[r] = colP[REV4[r] * 32 + lr];
        rfft512(reg, lane, tw);

        float mg[16];
#pragma unroll
        for (int r = 0; r < 16; r++) {
            float2 P = reg[r];
            float p2 = P.x * P.x + P.y * P.y;
            float re = P.x + 1e-8f;
            mg[r] = 10.0f * __logf(re * re + P.y * P.y);   // 20*ln|re+eps+i*im|
            float df = p2 - t2[r];
            dpark[w][(r << 5) | lane] = df * df;           // same thread reloads
        }

        const bool  lo  = (lane < 16);
        const bool  dup = (c >= 1 && c <= 255);
        const bool  act = lo || dup;
        float sx   = (float)((c + 256) & 511) - 255.5f;
        float sxm  = 0.5f - (float)c;
        const float q  = lo ? sx * sx : sxm * sxm;

        // ---- quantity pass macro: gather mirror values, pair-sum, bin runs
#define QPASS(X, ARR, DOCNT_CNT)                                              \
        {                                                                     \
            float wm[16];                                                     \
            wm[0] = __shfl_sync(FULLM, X[0], (32 - lane) & 31);               \
            _Pragma("unroll")                                                 \
            for (int r = 1; r < 16; r++)                                      \
                wm[r] = __shfl_xor_sync(FULLM, X[16 - r], 31);                \
            float pm[16];                                                     \
            _Pragma("unroll")                                                 \
            for (int r = 0; r < 16; r++) {                                    \
                float s1 = __shfl_xor_sync(FULLM, X[15 - r], 31);             \
                float s2 = __shfl_xor_sync(FULLM, wm[15 - r], 31);            \
                pm[r] = lo ? (X[r] + s1) : (wm[r] + s2);                      \
            }                                                                 \
            int pb = -1; float acc = 0.f, cac = 0.f;                          \
            _Pragma("unroll")                                                 \
            for (int r = 0; r < 16; r++) {                                    \
                int ky = (lane << 4) + r;                                     \
                float sy = (float)((ky + 256) & 511) - 255.5f;                \
                int b = ibin(q + sy * sy);                                    \
                if (b != pb) {                                                \
                    if (pb >= 0 && act) {                                     \
                        atomicAdd(ARR + pb, acc);                             \
                        if (DOCNT_CNT) atomicAdd(scn + pb, cac);              \
                    }                                                         \
                    pb = b; acc = 0.f; cac = 0.f;                             \
                }                                                             \
                acc += pm[r]; cac += 2.0f;                                    \
            }                                                                 \
            if (pb >= 0 && act) {                                             \
                atomicAdd(ARR + pb, acc);                                     \
                if (DOCNT_CNT) atomicAdd(scn + pb, cac);                      \
            }                                                                 \
        }

        QPASS(mg, sbm, docnt)

        float ddv[16];
#pragma unroll
        for (int r = 0; r < 16; r++) ddv[r] = dpark[w][(r << 5) | lane];
        QPASS(ddv, sbd, false)
#undef QPASS
    }
    __syncthreads();

    for (int i = tid; i < NBINS; i += 256) {
        atomicAdd(&g_Smag[img][i], sbm[i]);
        atomicAdd(&g_Sd[img][i],   sbd[i]);
        if (docnt) atomicAdd(&g_cnt[i], scn[i]);
    }

    // ---- fused finalize: last block to flush does the per-image reduce ----
    __syncthreads();
    if (tid == 0) {
        __threadfence();
        slast = (atomicAdd(&g_done, 1u) == (unsigned)(gridDim.x - 1)) ? 1u : 0u;
    }
    __syncthreads();
    if (!slast) return;
    __threadfence();   // acquire: all other blocks' flushes visible

    double acc = 0.0;
#pragma unroll
    for (int j = 0; j < 3; j++) {
        int im = w + (j << 3);
        float bm[12];
        float mn = CUDART_INF_F, mx = -CUDART_INF_F;
#pragma unroll
        for (int i = 0; i < 12; i++) {
            int b = lane + (i << 5);
            float v = 0.0f;
            if (b < NBINS) v = g_Smag[im][b] / g_cnt[b];
            bm[i] = v;
            if (b >= 1 && b <= 360) { mn = fminf(mn, v); mx = fmaxf(mx, v); }
        }
#pragma unroll
        for (int o = 16; o > 0; o >>= 1) {
            mn = fminf(mn, __shfl_xor_sync(FULLM, mn, o));
            mx = fmaxf(mx, __shfl_xor_sync(FULLM, mx, o));
        }
        float bm1 = __shfl_sync(FULLM, bm[0], 1);   // bin-1 mean (for bin 0)
#pragma unroll
        for (int i = 0; i < 12; i++) {
            int b = lane + (i << 5);
            if (b < NBINS) {
                float psdext;
                if (b == 361)    psdext = 0.0f;
                else {
                    float base = (b == 0) ? bm1 : bm[i];  // psd_ext[0]==psd_ext[1]
                    psdext = (base - mn) / (mx - mn);
                }
                float wv = 1.0f - psdext;
                if (!(wv == wv)) wv = 0.0f;               // nan -> 0
                wv = fminf(fmaxf(wv, 0.0f), 1.0f);        // clip
                acc += (double)wv * (double)g_Sd[im][b];
            }
        }
    }
#pragma unroll
    for (int o = 16; o > 0; o >>= 1)
        acc += __shfl_xor_sync(FULLM, acc, o);
    if (lane == 0) wacc[w] = acc;
    __syncthreads();
    if (tid == 0) {
        double tot = 0.0;
        for (int i = 0; i < 8; i++) tot += wacc[i];
        out[0] = (float)(tot / ((double)NIMG * (double)NPIX));
    }
}

// ---------------------------------------------------------------------------
extern "C" void kernel_launch(void* const* d_in, const int* in_sizes, int n_in,
                              void* d_out, int out_size) {
    const float* pred = (const float*)d_in[0];
    const float* tgt  = (const float*)d_in[1];
    float* out = (float*)d_out;

    kfft_rows<<<48 * 32, 256>>>(pred, tgt);
    kfft_cols<<<NIMG * 33, 256>>>(out);
}

// round 15
// speedup vs baseline: 2.0454x; 1.0418x over previous
#include <cuda_runtime.h>
#include <math_constants.h>

#define HH 512
#define WW 512
#define NIMG 24          // 8 * 3 image slices per tensor
#define NBINS 362
#define NPIX (HH * WW)
#define NK 257           // stored spectrum columns 0..256 (Hermitian)
#define FULLM 0xffffffffu

// ---------------------------------------------------------------------------
// Transposed scratch: g_fftT[tens][img][k*512 + y] = row-FFT(row y)[freq k]
__device__ float2 g_fftT[2][NIMG][NK * HH];
__device__ float  g_Smag[NIMG][NBINS];
__device__ float  g_Sd[NIMG][NBINS];
__device__ float  g_cnt[NBINS];
__device__ unsigned g_done;

__device__ __forceinline__ int rev5(int x) { return (int)(__brev((unsigned)x) >> 27); }

__device__ __forceinline__ float2 cmul(float2 a, float2 b) {
    return make_float2(a.x * b.x - a.y * b.y, a.x * b.y + a.y * b.x);
}

// Exact floor(sqrt(rsq)) for rsq = M + 0.5 (exactly representable; gap to any
// integer root >= 0.25/361 >> MUFU.SQRT error) -> plain truncation is exact.
__device__ __forceinline__ int ibin(float rsq) {
    float ra;
    asm("sqrt.approx.f32 %0, %1;" : "=f"(ra) : "f"(rsq));
    return (int)ra;
}

// ---------------------------------------------------------------------------
// Fully register-resident 512-pt radix-2 DIT FFT per warp.
// Input: reg[r] = x[rev9(lane*16+r)]. Output: natural order, t = lane*16+r.
__device__ __forceinline__ void rfft512(float2 reg[16], int lane, const float2* tw) {
    const float c16[8] = { 1.f,  0.92387953f,  0.70710678f,  0.38268343f,
                           0.f, -0.38268343f, -0.70710678f, -0.92387953f };
    const float s16[8] = { 0.f, -0.38268343f, -0.70710678f, -0.92387953f,
                          -1.f, -0.92387953f, -0.70710678f, -0.38268343f };
#pragma unroll
    for (int s = 1; s <= 4; s++) {
        const int half = 1 << (s - 1);
#pragma unroll
        for (int b = 0; b < 8; b++) {
            int j  = b & (half - 1);
            int i0 = ((b >> (s - 1)) << s) + j;
            int i1 = i0 + half;
            int ji = j << (4 - s);
            float2 u = reg[i0], v = reg[i1];
            float2 wv = make_float2(v.x * c16[ji] - v.y * s16[ji],
                                    v.x * s16[ji] + v.y * c16[ji]);
            reg[i0] = make_float2(u.x + wv.x, u.y + wv.y);
            reg[i1] = make_float2(u.x - wv.x, u.y - wv.y);
        }
    }
#pragma unroll
    for (int s = 5; s <= 9; s++) {
        const int L = 1 << (s - 5);
        const bool  up  = (lane & L) != 0;
        const float sgn = up ? -1.f : 1.f;
        float2 E = make_float2(1.f, 0.f);
        if (s >= 7) E = tw[(lane & (L - 1)) << (13 - s)];
#pragma unroll
        for (int r = 0; r < 16; r++) {
            float2 x = reg[r];
            float2 wx;
            if (s == 5)      wx = cmul(x, tw[r << 4]);
            else if (s == 6) wx = cmul(x, tw[((lane & 1) << 7) + (r << 3)]);
            else             wx = cmul(cmul(x, E), tw[(r << 4) >> (s - 5)]);
            float yx = up ? wx.x : x.x;
            float yy = up ? wx.y : x.y;
            float ox = __shfl_xor_sync(FULLM, yx, L);
            float oy = __shfl_xor_sync(FULLM, yy, L);
            reg[r].x = fmaf(sgn, yx, ox);
            reg[r].y = fmaf(sgn, yy, oy);
        }
    }
}

// ---------------------------------------------------------------------------
// Pass 1: row FFTs (2 real rows packed per complex FFT). Input loaded with
// __ldcs (evict-first) so the 100 MB input stream does NOT evict our 50 MB
// scratch from L2 — the cols pass then reads scratch at L2 latency.
__global__ void __launch_bounds__(256) kfft_rows(const float* __restrict__ pred,
                                                 const float* __restrict__ tgt) {
    __shared__ float2 ttile[NK * 17];   // [k][y ^ ((k>>4)&15)], stride 17
    __shared__ float2 tw[256];
    const int REV4[16] = {0,8,4,12,2,10,6,14,1,9,5,13,3,11,7,15};

    int tid = threadIdx.x;
    int bid = blockIdx.x;

    if (bid < 18) {   // folded accumulator zeroing (rows precede cols)
        for (int i = bid * 256 + tid; i < NIMG * NBINS; i += 18 * 256) {
            ((float*)g_Smag)[i] = 0.0f;
            ((float*)g_Sd)[i]   = 0.0f;
        }
        if (bid == 0) {
            for (int i = tid; i < NBINS; i += 256) g_cnt[i] = 0.0f;
            if (tid == 0) g_done = 0u;
        }
    }
    {
        float sn, cs;
        sincospif(-(float)tid / 256.0f, &sn, &cs);
        tw[tid] = make_float2(cs, sn);
    }

    int slice = bid >> 5;
    int pg    = bid & 31;
    int tens  = (slice >= NIMG) ? 1 : 0;
    int img   = tens ? slice - NIMG : slice;
    const float* src = tens ? tgt : pred;

    int w = tid >> 5, lane = tid & 31;
    int y0 = pg * 16;
    const float* rowA = src + ((size_t)img << 18) + ((size_t)(y0 + 2 * w) << 9);
    const float* rowB = rowA + HH;
    int lr = rev5(lane);

    float2 reg[16];
#pragma unroll
    for (int r = 0; r < 16; r++) {
        int s = REV4[r] * 32 + lr;
        reg[r] = make_float2(__ldcs(rowA + s), __ldcs(rowB + s));
    }
    __syncthreads();                 // tw ready

    rfft512(reg, lane, tw);

    // Hermitian unpack: A[k]=(Z1+conj(Z2))/2, B[k]=(Z1-conj(Z2))/2i
    {
        int k0 = lane << 4;
        int p0 = (32 - lane) & 31;
        float zx = __shfl_sync(FULLM, reg[0].x, p0);
        float zy = __shfl_sync(FULLM, reg[0].y, p0);
        if (k0 <= 256) {
            int fk = (k0 >> 4) & 15;
            float2 Z1 = reg[0];
            ttile[k0 * 17 + ((2 * w) ^ fk)]       = make_float2(0.5f * (Z1.x + zx), 0.5f * (Z1.y - zy));
            ttile[k0 * 17 + (((2 * w) ^ fk) ^ 1)] = make_float2(0.5f * (Z1.y + zy), 0.5f * (zx - Z1.x));
        }
    }
#pragma unroll
    for (int r = 1; r < 16; r++) {
        float zx = __shfl_sync(FULLM, reg[16 - r].x, lane ^ 31);
        float zy = __shfl_sync(FULLM, reg[16 - r].y, lane ^ 31);
        if (lane < 16) {
            int k = (lane << 4) + r;
            float2 Z1 = reg[r];
            ttile[k * 17 + ((2 * w) ^ lane)] =
                make_float2(0.5f * (Z1.x + zx), 0.5f * (Z1.y - zy));
        } else {
            int L = lane ^ 31;
            int k = (L << 4) + 16 - r;
            float2 Z2 = reg[r];
            ttile[k * 17 + (((2 * w) ^ L) ^ 1)] =
                make_float2(0.5f * (zy + Z2.y), 0.5f * (Z2.x - zx));
        }
    }
    __syncthreads();

    float2* outp = g_fftT[tens][img];
    for (int i = tid; i < NK * 16; i += 256) {
        int k = i >> 4, y = i & 15;
        outp[k * 512 + y0 + y] = ttile[k * 17 + (y ^ ((k >> 4) & 15))];
    }
}

// ---------------------------------------------------------------------------
// Pass 2: column register FFTs for kx = 0..256. Single merged binning pass
// (mag + d together): mirror-symmetry pair aggregation where the second pair
// member for upper lanes is the LOCAL register X[r+1] (shuffle identity),
// halving ATOMS lane-ops at minimal shuffle cost. Scratch read with __ldcs.
__global__ void __launch_bounds__(256, 3) kfft_cols(float* __restrict__ out) {
    __shared__ float2 tw[256];
    __shared__ float  sbm[NBINS], sbd[NBINS], scn[NBINS];
    __shared__ double wacc[8];
    __shared__ unsigned slast;
    const int REV4[16] = {0,8,4,12,2,10,6,14,1,9,5,13,3,11,7,15};

    int tid = threadIdx.x;
    {
        float sn, cs;
        sincospif(-(float)tid / 256.0f, &sn, &cs);
        tw[tid] = make_float2(cs, sn);
    }
    for (int i = tid; i < NBINS; i += 256) { sbm[i] = 0.0f; sbd[i] = 0.0f; scn[i] = 0.0f; }
    __syncthreads();

    int bid = blockIdx.x;
    int img = bid / 33;
    int c0  = (bid % 33) << 3;
    bool docnt = (img == 0);

    int w = tid >> 5, lane = tid & 31;
    int c = c0 + w;

    if (c <= 256) {
        const float2* colP = &g_fftT[0][img][(size_t)c * 512];
        const float2* colT = &g_fftT[1][img][(size_t)c * 512];
        int lr = rev5(lane);

        float2 reg[16];
        // target: |T|^2 in registers
#pragma unroll
        for (int r = 0; r < 16; r++) reg[r] = __ldcs(colT + REV4[r] * 32 + lr);
        rfft512(reg, lane, tw);
        float t2[16];
#pragma unroll
        for (int r = 0; r < 16; r++) t2[r] = reg[r].x * reg[r].x + reg[r].y * reg[r].y;

        // pred
#pragma unroll
        for (int r = 0; r < 16; r++) reg[r] = __ldcs(colP + REV4[r] * 32 + lr);
        rfft512(reg, lane, tw);

        float mg[16], dd[16];
#pragma unroll
        for (int r = 0; r < 16; r++) {
            float2 P = reg[r];
            float p2 = P.x * P.x + P.y * P.y;
            float re = P.x + 1e-8f;
            mg[r] = 10.0f * __logf(re * re + P.y * P.y);   // 20*ln|re+eps+i*im|
            float df = p2 - t2[r];
            dd[r] = df * df;
        }

        const bool  lo  = (lane < 16);
        const bool  dup = (c >= 1 && c <= 255);
        const bool  act = lo || dup;   // lanes 16-31 bin the mirror column
        float sx   = (float)((c + 256) & 511) - 255.5f;
        float sxm  = 0.5f - (float)c;
        const float q  = lo ? sx * sx : sxm * sxm;

        // merged single-pass pair-aggregated binning:
        //  lower lane L, arc pos ky=16L+r: pair = X[r] + X_partner(511-ky)
        //      partner at lane L^31, reg 15-r  -> one shfl_xor
        //  upper lane U, arc pos ky=16U+r (mirror column): pair =
        //      wm (= main elem 512-ky, at lane U^31 reg 16-r) + X[r+1] (LOCAL)
        int   pb = -1;
        float am = 0.f, ad = 0.f, cn = 0.f;
#pragma unroll
        for (int r = 0; r < 16; r++) {
            float s1m = __shfl_xor_sync(FULLM, mg[15 - r], 31);
            float s1d = __shfl_xor_sync(FULLM, dd[15 - r], 31);
            float wmm, wmd;
            if (r == 0) {
                int p0 = (32 - lane) & 31;
                wmm = __shfl_sync(FULLM, mg[0], p0);
                wmd = __shfl_sync(FULLM, dd[0], p0);
            } else {
                wmm = __shfl_xor_sync(FULLM, mg[16 - r], 31);
                wmd = __shfl_xor_sync(FULLM, dd[16 - r], 31);
            }
            float s2m, s2d;
            if (r < 15) { s2m = mg[r + 1]; s2d = dd[r + 1]; }
            else {
                int p1 = (lane + 1) & 31;
                s2m = __shfl_sync(FULLM, mg[0], p1);
                s2d = __shfl_sync(FULLM, dd[0], p1);
            }
            float pmm = lo ? (mg[r] + s1m) : (wmm + s2m);
            float pmd = lo ? (dd[r] + s1d) : (wmd + s2d);

            int ky = (lane << 4) + r;
            float sy = (float)((ky + 256) & 511) - 255.5f;
            int b = ibin(q + sy * sy);
            if (b != pb) {
                if (pb >= 0 && act) {
                    atomicAdd(sbm + pb, am);
                    atomicAdd(sbd + pb, ad);
                    if (docnt) atomicAdd(scn + pb, cn);
                }
                pb = b; am = 0.f; ad = 0.f; cn = 0.f;
            }
            am += pmm; ad += pmd; cn += 2.0f;
        }
        if (pb >= 0 && act) {
            atomicAdd(sbm + pb, am);
            atomicAdd(sbd + pb, ad);
            if (docnt) atomicAdd(scn + pb, cn);
        }
    }
    __syncthreads();

    for (int i = tid; i < NBINS; i += 256) {
        atomicAdd(&g_Smag[img][i], sbm[i]);
        atomicAdd(&g_Sd[img][i],   sbd[i]);
        if (docnt) atomicAdd(&g_cnt[i], scn[i]);
    }

    // ---- fused finalize: last block to flush does the per-image reduce ----
    __syncthreads();
    if (tid == 0) {
        __threadfence();
        slast = (atomicAdd(&g_done, 1u) == (unsigned)(gridDim.x - 1)) ? 1u : 0u;
    }
    __syncthreads();
    if (!slast) return;
    __threadfence();   // acquire: all other blocks' flushes visible

    double acc = 0.0;
#pragma unroll
    for (int j = 0; j < 3; j++) {
        int im = w + (j << 3);
        float bm[12];
        float mn = CUDART_INF_F, mx = -CUDART_INF_F;
#pragma unroll
        for (int i = 0; i < 12; i++) {
            int b = lane + (i << 5);
            float v = 0.0f;
            if (b < NBINS) v = g_Smag[im][b] / g_cnt[b];
            bm[i] = v;
            if (b >= 1 && b <= 360) { mn = fminf(mn, v); mx = fmaxf(mx, v); }
        }
#pragma unroll
        for (int o = 16; o > 0; o >>= 1) {
            mn = fminf(mn, __shfl_xor_sync(FULLM, mn, o));
            mx = fmaxf(mx, __shfl_xor_sync(FULLM, mx, o));
        }
        float bm1 = __shfl_sync(FULLM, bm[0], 1);   // bin-1 mean (for bin 0)
#pragma unroll
        for (int i = 0; i < 12; i++) {
            int b = lane + (i << 5);
            if (b < NBINS) {
                float psdext;
                if (b == 361)    psdext = 0.0f;
                else {
                    float base = (b == 0) ? bm1 : bm[i];  // psd_ext[0]==psd_ext[1]
                    psdext = (base - mn) / (mx - mn);
                }
                float wv = 1.0f - psdext;
                if (!(wv == wv)) wv = 0.0f;               // nan -> 0
                wv = fminf(fmaxf(wv, 0.0f), 1.0f);        // clip
                acc += (double)wv * (double)g_Sd[im][b];
            }
        }
    }
#pragma unroll
    for (int o = 16; o > 0; o >>= 1)
        acc += __shfl_xor_sync(FULLM, acc, o);
    if (lane == 0) wacc[w] = acc;
    __syncthreads();
    if (tid == 0) {
        double tot = 0.0;
        for (int i = 0; i < 8; i++) tot += wacc[i];
        out[0] = (float)(tot / ((double)NIMG * (double)NPIX));
    }
}

// ---------------------------------------------------------------------------
extern "C" void kernel_launch(void* const* d_in, const int* in_sizes, int n_in,
                              void* d_out, int out_size) {
    const float* pred = (const float*)d_in[0];
    const float* tgt  = (const float*)d_in[1];
    float* out = (float*)d_out;

    kfft_rows<<<48 * 32, 256>>>(pred, tgt);
    kfft_cols<<<NIMG * 33, 256>>>(out);
}

// round 16
// speedup vs baseline: 2.1331x; 1.0429x over previous
#include <cuda_runtime.h>
#include <cuda_fp16.h>
#include <math_constants.h>

#define HH 512
#define WW 512
#define NIMG 24          // 8 * 3 image slices per tensor
#define NBINS 362
#define NPIX (HH * WW)
#define NK 257           // stored spectrum columns 0..256 (Hermitian)
#define FULLM 0xffffffffu

// ---------------------------------------------------------------------------
// Transposed scratch (fp16): g_fftT[tens][img][k*512+y] = row-FFT[freq k](row y)
__device__ __half2 g_fftT[2][NIMG][NK * HH];
__device__ float  g_Smag[NIMG][NBINS];
__device__ float  g_Sd[NIMG][NBINS];
__device__ float  g_cnt[NBINS];
__device__ unsigned g_done;

__device__ __forceinline__ int rev5(int x) { return (int)(__brev((unsigned)x) >> 27); }

__device__ __forceinline__ float2 cmul(float2 a, float2 b) {
    return make_float2(a.x * b.x - a.y * b.y, a.x * b.y + a.y * b.x);
}

// Exact floor(sqrt(rsq)) for rsq = M + 0.5 (exactly representable; gap to any
// integer root >= 0.25/361 >> MUFU.SQRT error) -> plain truncation is exact.
__device__ __forceinline__ int ibin(float rsq) {
    float ra;
    asm("sqrt.approx.f32 %0, %1;" : "=f"(ra) : "f"(rsq));
    return (int)ra;
}

// ---------------------------------------------------------------------------
// Fully register-resident 512-pt radix-2 DIT FFT per warp.
// Input: reg[r] = x[rev9(lane*16+r)]. Output: natural order, t = lane*16+r.
__device__ __forceinline__ void rfft512(float2 reg[16], int lane, const float2* tw) {
    const float c16[8] = { 1.f,  0.92387953f,  0.70710678f,  0.38268343f,
                           0.f, -0.38268343f, -0.70710678f, -0.92387953f };
    const float s16[8] = { 0.f, -0.38268343f, -0.70710678f, -0.92387953f,
                          -1.f, -0.92387953f, -0.70710678f, -0.38268343f };
#pragma unroll
    for (int s = 1; s <= 4; s++) {
        const int half = 1 << (s - 1);
#pragma unroll
        for (int b = 0; b < 8; b++) {
            int j  = b & (half - 1);
            int i0 = ((b >> (s - 1)) << s) + j;
            int i1 = i0 + half;
            int ji = j << (4 - s);
            float2 u = reg[i0], v = reg[i1];
            float2 wv = make_float2(v.x * c16[ji] - v.y * s16[ji],
                                    v.x * s16[ji] + v.y * c16[ji]);
            reg[i0] = make_float2(u.x + wv.x, u.y + wv.y);
            reg[i1] = make_float2(u.x - wv.x, u.y - wv.y);
        }
    }
#pragma unroll
    for (int s = 5; s <= 9; s++) {
        const int L = 1 << (s - 5);
        const bool  up  = (lane & L) != 0;
        const float sgn = up ? -1.f : 1.f;
        float2 E = make_float2(1.f, 0.f);
        if (s >= 7) E = tw[(lane & (L - 1)) << (13 - s)];
#pragma unroll
        for (int r = 0; r < 16; r++) {
            float2 x = reg[r];
            float2 wx;
            if (s == 5)      wx = cmul(x, tw[r << 4]);
            else if (s == 6) wx = cmul(x, tw[((lane & 1) << 7) + (r << 3)]);
            else             wx = cmul(cmul(x, E), tw[(r << 4) >> (s - 5)]);
            float yx = up ? wx.x : x.x;
            float yy = up ? wx.y : x.y;
            float ox = __shfl_xor_sync(FULLM, yx, L);
            float oy = __shfl_xor_sync(FULLM, yy, L);
            reg[r].x = fmaf(sgn, yx, ox);
            reg[r].y = fmaf(sgn, yy, oy);
        }
    }
}

// ---------------------------------------------------------------------------
// Pass 1: row FFTs (2 real rows packed per complex FFT). Input loaded with
// __ldcs (evict-first); spectrum stored transposed as fp16 (half traffic,
// L2-resident for the cols pass).
__global__ void __launch_bounds__(256) kfft_rows(const float* __restrict__ pred,
                                                 const float* __restrict__ tgt) {
    __shared__ float2 ttile[NK * 17];   // [k][y ^ ((k>>4)&15)], stride 17
    __shared__ float2 tw[256];
    const int REV4[16] = {0,8,4,12,2,10,6,14,1,9,5,13,3,11,7,15};

    int tid = threadIdx.x;
    int bid = blockIdx.x;

    if (bid < 18) {   // folded accumulator zeroing (rows precede cols)
        for (int i = bid * 256 + tid; i < NIMG * NBINS; i += 18 * 256) {
            ((float*)g_Smag)[i] = 0.0f;
            ((float*)g_Sd)[i]   = 0.0f;
        }
        if (bid == 0) {
            for (int i = tid; i < NBINS; i += 256) g_cnt[i] = 0.0f;
            if (tid == 0) g_done = 0u;
        }
    }
    {
        float sn, cs;
        sincospif(-(float)tid / 256.0f, &sn, &cs);
        tw[tid] = make_float2(cs, sn);
    }

    int slice = bid >> 5;
    int pg    = bid & 31;
    int tens  = (slice >= NIMG) ? 1 : 0;
    int img   = tens ? slice - NIMG : slice;
    const float* src = tens ? tgt : pred;

    int w = tid >> 5, lane = tid & 31;
    int y0 = pg * 16;
    const float* rowA = src + ((size_t)img << 18) + ((size_t)(y0 + 2 * w) << 9);
    const float* rowB = rowA + HH;
    int lr = rev5(lane);

    float2 reg[16];
#pragma unroll
    for (int r = 0; r < 16; r++) {
        int s = REV4[r] * 32 + lr;
        reg[r] = make_float2(__ldcs(rowA + s), __ldcs(rowB + s));
    }
    __syncthreads();                 // tw ready

    rfft512(reg, lane, tw);

    // Hermitian unpack: A[k]=(Z1+conj(Z2))/2, B[k]=(Z1-conj(Z2))/2i
    {
        int k0 = lane << 4;
        int p0 = (32 - lane) & 31;
        float zx = __shfl_sync(FULLM, reg[0].x, p0);
        float zy = __shfl_sync(FULLM, reg[0].y, p0);
        if (k0 <= 256) {
            int fk = (k0 >> 4) & 15;
            float2 Z1 = reg[0];
            ttile[k0 * 17 + ((2 * w) ^ fk)]       = make_float2(0.5f * (Z1.x + zx), 0.5f * (Z1.y - zy));
            ttile[k0 * 17 + (((2 * w) ^ fk) ^ 1)] = make_float2(0.5f * (Z1.y + zy), 0.5f * (zx - Z1.x));
        }
    }
#pragma unroll
    for (int r = 1; r < 16; r++) {
        float zx = __shfl_sync(FULLM, reg[16 - r].x, lane ^ 31);
        float zy = __shfl_sync(FULLM, reg[16 - r].y, lane ^ 31);
        if (lane < 16) {
            int k = (lane << 4) + r;
            float2 Z1 = reg[r];
            ttile[k * 17 + ((2 * w) ^ lane)] =
                make_float2(0.5f * (Z1.x + zx), 0.5f * (Z1.y - zy));
        } else {
            int L = lane ^ 31;
            int k = (L << 4) + 16 - r;
            float2 Z2 = reg[r];
            ttile[k * 17 + (((2 * w) ^ L) ^ 1)] =
                make_float2(0.5f * (zy + Z2.y), 0.5f * (Z2.x - zx));
        }
    }
    __syncthreads();

    // coalesced transposed store (fp16): 16 consecutive y per k
    __half2* outp = g_fftT[tens][img];
    for (int i = tid; i < NK * 16; i += 256) {
        int k = i >> 4, y = i & 15;
        float2 v = ttile[k * 17 + (y ^ ((k >> 4) & 15))];
        outp[k * 512 + y0 + y] = __floats2half2_rn(v.x, v.y);
    }
}

// ---------------------------------------------------------------------------
// Pass 2: column register FFTs for kx = 0..256 (fp16 scratch loads), single
// merged pair-aggregated binning pass, fused finalize in the last block.
__global__ void __launch_bounds__(256, 3) kfft_cols(float* __restrict__ out) {
    __shared__ float2 tw[256];
    __shared__ float  sbm[NBINS], sbd[NBINS], scn[NBINS];
    __shared__ double wacc[8];
    __shared__ unsigned slast;
    const int REV4[16] = {0,8,4,12,2,10,6,14,1,9,5,13,3,11,7,15};

    int tid = threadIdx.x;
    {
        float sn, cs;
        sincospif(-(float)tid / 256.0f, &sn, &cs);
        tw[tid] = make_float2(cs, sn);
    }
    for (int i = tid; i < NBINS; i += 256) { sbm[i] = 0.0f; sbd[i] = 0.0f; scn[i] = 0.0f; }
    __syncthreads();

    int bid = blockIdx.x;
    int img = bid / 33;
    int c0  = (bid % 33) << 3;
    bool docnt = (img == 0);

    int w = tid >> 5, lane = tid & 31;
    int c = c0 + w;

    if (c <= 256) {
        const __half2* colP = &g_fftT[0][img][(size_t)c * 512];
        const __half2* colT = &g_fftT[1][img][(size_t)c * 512];
        int lr = rev5(lane);

        float2 reg[16];
        // target: |T|^2 in registers
#pragma unroll
        for (int r = 0; r < 16; r++)
            reg[r] = __half22float2(__ldcs(colT + REV4[r] * 32 + lr));
        rfft512(reg, lane, tw);
        float t2[16];
#pragma unroll
        for (int r = 0; r < 16; r++) t2[r] = reg[r].x * reg[r].x + reg[r].y * reg[r].y;

        // pred
#pragma unroll
        for (int r = 0; r < 16; r++)
            reg[r] = __half22float2(__ldcs(colP + REV4[r] * 32 + lr));
        rfft512(reg, lane, tw);

        float mg[16], dd[16];
#pragma unroll
        for (int r = 0; r < 16; r++) {
            float2 P = reg[r];
            float p2 = P.x * P.x + P.y * P.y;
            float re = P.x + 1e-8f;
            mg[r] = 10.0f * __logf(re * re + P.y * P.y);   // 20*ln|re+eps+i*im|
            float df = p2 - t2[r];
            dd[r] = df * df;
        }

        const bool  lo  = (lane < 16);
        const bool  dup = (c >= 1 && c <= 255);
        const bool  act = lo || dup;   // lanes 16-31 bin the mirror column
        float sx   = (float)((c + 256) & 511) - 255.5f;
        float sxm  = 0.5f - (float)c;
        const float q  = lo ? sx * sx : sxm * sxm;

        // merged single-pass pair-aggregated binning (see round-14 derivation)
        int   pb = -1;
        float am = 0.f, ad = 0.f, cn = 0.f;
#pragma unroll
        for (int r = 0; r < 16; r++) {
            float s1m = __shfl_xor_sync(FULLM, mg[15 - r], 31);
            float s1d = __shfl_xor_sync(FULLM, dd[15 - r], 31);
            float wmm, wmd;
            if (r == 0) {
                int p0 = (32 - lane) & 31;
                wmm = __shfl_sync(FULLM, mg[0], p0);
                wmd = __shfl_sync(FULLM, dd[0], p0);
            } else {
                wmm = __shfl_xor_sync(FULLM, mg[16 - r], 31);
                wmd = __shfl_xor_sync(FULLM, dd[16 - r], 31);
            }
            float s2m, s2d;
            if (r < 15) { s2m = mg[r + 1]; s2d = dd[r + 1]; }
            else {
                int p1 = (lane + 1) & 31;
                s2m = __shfl_sync(FULLM, mg[0], p1);
                s2d = __shfl_sync(FULLM, dd[0], p1);
            }
            float pmm = lo ? (mg[r] + s1m) : (wmm + s2m);
            float pmd = lo ? (dd[r] + s1d) : (wmd + s2d);

            int ky = (lane << 4) + r;
            float sy = (float)((ky + 256) & 511) - 255.5f;
            int b = ibin(q + sy * sy);
            if (b != pb) {
                if (pb >= 0 && act) {
                    atomicAdd(sbm + pb, am);
                    atomicAdd(sbd + pb, ad);
                    if (docnt) atomicAdd(scn + pb, cn);
                }
                pb = b; am = 0.f; ad = 0.f; cn = 0.f;
            }
            am += pmm; ad += pmd; cn += 2.0f;
        }
        if (pb >= 0 && act) {
            atomicAdd(sbm + pb, am);
            atomicAdd(sbd + pb, ad);
            if (docnt) atomicAdd(scn + pb, cn);
        }
    }
    __syncthreads();

    for (int i = tid; i < NBINS; i += 256) {
        atomicAdd(&g_Smag[img][i], sbm[i]);
        atomicAdd(&g_Sd[img][i],   sbd[i]);
        if (docnt) atomicAdd(&g_cnt[i], scn[i]);
    }

    // ---- fused finalize: last block to flush does the per-image reduce ----
    __syncthreads();
    if (tid == 0) {
        __threadfence();
        slast = (atomicAdd(&g_done, 1u) == (unsigned)(gridDim.x - 1)) ? 1u : 0u;
    }
    __syncthreads();
    if (!slast) return;
    __threadfence();   // acquire: all other blocks' flushes visible

    double acc = 0.0;
#pragma unroll
    for (int j = 0; j < 3; j++) {
        int im = w + (j << 3);
        float bm[12];
        float mn = CUDART_INF_F, mx = -CUDART_INF_F;
#pragma unroll
        for (int i = 0; i < 12; i++) {
            int b = lane + (i << 5);
            float v = 0.0f;
            if (b < NBINS) v = g_Smag[im][b] / g_cnt[b];
            bm[i] = v;
            if (b >= 1 && b <= 360) { mn = fminf(mn, v); mx = fmaxf(mx, v); }
        }
#pragma unroll
        for (int o = 16; o > 0; o >>= 1) {
            mn = fminf(mn, __shfl_xor_sync(FULLM, mn, o));
            mx = fmaxf(mx, __shfl_xor_sync(FULLM, mx, o));
        }
        float bm1 = __shfl_sync(FULLM, bm[0], 1);   // bin-1 mean (for bin 0)
#pragma unroll
        for (int i = 0; i < 12; i++) {
            int b = lane + (i << 5);
            if (b < NBINS) {
                float psdext;
                if (b == 361)    psdext = 0.0f;
                else {
                    float base = (b == 0) ? bm1 : bm[i];  // psd_ext[0]==psd_ext[1]
                    psdext = (base - mn) / (mx - mn);
                }
                float wv = 1.0f - psdext;
                if (!(wv == wv)) wv = 0.0f;               // nan -> 0
                wv = fminf(fmaxf(wv, 0.0f), 1.0f);        // clip
                acc += (double)wv * (double)g_Sd[im][b];
            }
        }
    }
#pragma unroll
    for (int o = 16; o > 0; o >>= 1)
        acc += __shfl_xor_sync(FULLM, acc, o);
    if (lane == 0) wacc[w] = acc;
    __syncthreads();
    if (tid == 0) {
        double tot = 0.0;
        for (int i = 0; i < 8; i++) tot += wacc[i];
        out[0] = (float)(tot / ((double)NIMG * (double)NPIX));
    }
}

// ---------------------------------------------------------------------------
extern "C" void kernel_launch(void* const* d_in, const int* in_sizes, int n_in,
                              void* d_out, int out_size) {
    const float* pred = (const float*)d_in[0];
    const float* tgt  = (const float*)d_in[1];
    float* out = (float*)d_out;

    kfft_rows<<<48 * 32, 256>>>(pred, tgt);
    kfft_cols<<<NIMG * 33, 256>>>(out);
}